// round 3
// baseline (speedup 1.0000x reference)
#include <cuda_runtime.h>

#define BATCH   8192
#define ROW_LEN 128
#define DIM     128

__device__ float g_partials[BATCH];
__device__ unsigned int g_count = 0;

__global__ __launch_bounds__(128, 8)
void node2vec_fused_kernel(const void* __restrict__ rt_raw,
                           const float* __restrict__ X,
                           const int* __restrict__ m_ptr,
                           float* __restrict__ out) {
    const int b    = blockIdx.x;
    const int tid  = threadIdx.x;   // 0..127
    const int lane = tid & 31;
    const int warp = tid >> 5;      // 0..3

    __shared__ int   idx_s[ROW_LEN];
    __shared__ float x0s[DIM];
    __shared__ float scores[ROW_LEN];
    __shared__ float wred[4];
    __shared__ int   last_flag;

    const int* __restrict__ rt32 = (const int*)rt_raw;

    // Runtime dtype detection: int64 (< 2^31 values) => odd 32-bit words zero.
    const bool is64 = (rt32[1] == 0) & (rt32[3] == 0) & (rt32[5] == 0) & (rt32[7] == 0);

    const long long base = (long long)b * ROW_LEN;

    // Preload this row's 128 indices into shared (coalesced).
    idx_s[tid] = is64 ? rt32[2 * (base + tid)] : rt32[base + tid];

    // x0 = X[rt[b,0]]
    {
        const long long e0 = is64 ? (long long)rt32[2 * base] : (long long)rt32[base];
        x0s[tid] = __ldg(X + e0 * DIM + tid);
    }
    __syncthreads();

    const float4 x0v = reinterpret_cast<const float4*>(x0s)[lane];

    // Each warp computes dot(X[idx_s[l]], x0) for l = warp, warp+4, ...
    #pragma unroll 8
    for (int l = warp; l < ROW_LEN; l += 4) {
        const long long idx = idx_s[l];
        const float4 v = __ldg(reinterpret_cast<const float4*>(X + idx * DIM) + lane);
        float d = v.x * x0v.x + v.y * x0v.y + v.z * x0v.z + v.w * x0v.w;
        #pragma unroll
        for (int off = 16; off > 0; off >>= 1)
            d += __shfl_xor_sync(0xffffffffu, d, off);
        if (lane == 0) scores[l] = d;
    }
    __syncthreads();

    // Warp 0: softmax stats over 128 scores via shuffles (no smem tree).
    if (warp == 0) {
        const int m = m_ptr[0];     // low 32 bits of int32/int64 LE
        const float s0 = scores[lane];
        const float s1 = scores[lane + 32];
        const float s2 = scores[lane + 64];
        const float s3 = scores[lane + 96];

        float mx = fmaxf(fmaxf(s0, s1), fmaxf(s2, s3));
        #pragma unroll
        for (int off = 16; off > 0; off >>= 1)
            mx = fmaxf(mx, __shfl_xor_sync(0xffffffffu, mx, off));

        float e = __expf(s0 - mx) + __expf(s1 - mx) + __expf(s2 - mx) + __expf(s3 - mx);
        float p = 0.0f;
        if (lane >= 1 && lane <= m)        p += s0;
        if (lane + 32 <= m)                p += s1;
        if (lane + 64 <= m)                p += s2;
        if (lane + 96 <= m)                p += s3;
        #pragma unroll
        for (int off = 16; off > 0; off >>= 1) {
            e += __shfl_xor_sync(0xffffffffu, e, off);
            p += __shfl_xor_sync(0xffffffffu, p, off);
        }

        if (lane == 0) {
            const float lse = mx + __logf(e);
            g_partials[b] = (float)m * lse - p;
            __threadfence();
            const unsigned int t = atomicAdd(&g_count, 1u);
            last_flag = (t == (unsigned int)gridDim.x - 1u) ? 1 : 0;
        }
    }
    __syncthreads();

    // Last CTA: deterministic final sum of all partials.
    if (last_flag) {
        float s = 0.0f;
        const float4* __restrict__ p4 = reinterpret_cast<const float4*>(g_partials);
        #pragma unroll
        for (int i = tid; i < BATCH / 4; i += 128) {
            const float4 v = __ldcg(p4 + i);
            s += (v.x + v.y) + (v.z + v.w);
        }
        #pragma unroll
        for (int off = 16; off > 0; off >>= 1)
            s += __shfl_xor_sync(0xffffffffu, s, off);
        if (lane == 0) wred[warp] = s;
        __syncthreads();
        if (tid == 0) {
            const float total = (wred[0] + wred[1]) + (wred[2] + wred[3]);
            out[0] = total * (1.0f / (float)BATCH);
            g_count = 0u;   // reset for next graph replay
        }
    }
}

extern "C" void kernel_launch(void* const* d_in, const int* in_sizes, int n_in,
                              void* d_out, int out_size) {
    const void*  rt = d_in[0];                 // rt_batch [8192,128] int32 or int64
    const float* X  = (const float*)d_in[1];   // X float32 [100000,128]
    const int*   m  = (const int*)d_in[2];     // m scalar
    float* out = (float*)d_out;

    node2vec_fused_kernel<<<BATCH, 128>>>(rt, X, m, out);
}

// round 4
// speedup vs baseline: 1.9861x; 1.9861x over previous
#include <cuda_runtime.h>

#define BATCH   8192
#define ROW_LEN 128
#define DIM     128

__device__ float g_partials[BATCH];

__global__ __launch_bounds__(128, 10)
void node2vec_row_kernel(const void* __restrict__ rt_raw,
                         const float* __restrict__ X,
                         const int* __restrict__ m_ptr) {
    const int b    = blockIdx.x;
    const int tid  = threadIdx.x;   // 0..127
    const int lane = tid & 31;
    const int warp = tid >> 5;      // 0..3
    const int sub  = lane & 15;     // lane within half-warp
    const int hi   = lane >> 4;     // which half-warp (0/1)

    __shared__ int   idx_s[ROW_LEN];
    __shared__ float x0s[DIM];
    __shared__ float scores[ROW_LEN];

    const int* __restrict__ rt32 = (const int*)rt_raw;

    // Runtime dtype detection: int64 (<2^31 values) => odd 32-bit words zero.
    const bool is64 = (rt32[1] == 0) & (rt32[3] == 0) & (rt32[5] == 0) & (rt32[7] == 0);

    const long long base = (long long)b * ROW_LEN;

    // Preload this row's 128 indices into shared (one coalesced pass).
    idx_s[tid] = is64 ? rt32[2 * (base + tid)] : rt32[base + tid];

    // x0 = X[rt[b,0]]
    {
        const long long e0 = is64 ? (long long)rt32[2 * base] : (long long)rt32[base];
        x0s[tid] = __ldg(X + e0 * DIM + tid);
    }
    __syncthreads();

    // Each lane holds two float4 chunks of x0: chunk sub and chunk sub+16.
    const float4* __restrict__ x04 = reinterpret_cast<const float4*>(x0s);
    const float4 x0a = x04[sub];
    const float4 x0b = x04[sub + 16];

    // Each warp handles 32 rows, two per iteration (one per half-warp).
    // Row l = 8*k + 2*warp + hi, k = 0..15.
    #pragma unroll 4
    for (int k = 0; k < 16; ++k) {
        const int l = 8 * k + 2 * warp + hi;
        const long long idx = idx_s[l];
        const float4* __restrict__ r = reinterpret_cast<const float4*>(X + idx * DIM);
        const float4 va = __ldg(r + sub);
        const float4 vb = __ldg(r + sub + 16);
        float d = va.x * x0a.x + va.y * x0a.y + va.z * x0a.z + va.w * x0a.w
                + vb.x * x0b.x + vb.y * x0b.y + vb.z * x0b.z + vb.w * x0b.w;
        // 4-level reduction within each 16-lane half.
        #pragma unroll
        for (int off = 8; off > 0; off >>= 1)
            d += __shfl_xor_sync(0xffffffffu, d, off);
        if (sub == 0) scores[l] = d;
    }
    __syncthreads();

    // Warp 0: softmax stats over 128 scores via shuffles.
    if (warp == 0) {
        const int m = m_ptr[0];     // low 32 bits of int32/int64 LE
        const float s0 = scores[lane];
        const float s1 = scores[lane + 32];
        const float s2 = scores[lane + 64];
        const float s3 = scores[lane + 96];

        float mx = fmaxf(fmaxf(s0, s1), fmaxf(s2, s3));
        #pragma unroll
        for (int off = 16; off > 0; off >>= 1)
            mx = fmaxf(mx, __shfl_xor_sync(0xffffffffu, mx, off));

        float e = __expf(s0 - mx) + __expf(s1 - mx) + __expf(s2 - mx) + __expf(s3 - mx);
        float p = 0.0f;
        if (lane >= 1 && lane <= m)        p += s0;
        if (lane + 32 <= m)                p += s1;
        if (lane + 64 <= m)                p += s2;
        if (lane + 96 <= m)                p += s3;
        #pragma unroll
        for (int off = 16; off > 0; off >>= 1) {
            e += __shfl_xor_sync(0xffffffffu, e, off);
            p += __shfl_xor_sync(0xffffffffu, p, off);
        }

        if (lane == 0) {
            const float lse = mx + __logf(e);
            g_partials[b] = (float)m * lse - p;
        }
    }
}

__global__ __launch_bounds__(1024)
void node2vec_reduce_kernel(float* __restrict__ out) {
    __shared__ float wred[32];
    const int tid  = threadIdx.x;
    const int lane = tid & 31;
    const int warp = tid >> 5;
    // 8192 floats = 2048 float4; 1024 threads -> 2 float4 each.
    const float4* __restrict__ p4 = reinterpret_cast<const float4*>(g_partials);
    const float4 a = p4[tid];
    const float4 c = p4[tid + 1024];
    float s = (a.x + a.y) + (a.z + a.w) + (c.x + c.y) + (c.z + c.w);
    #pragma unroll
    for (int off = 16; off > 0; off >>= 1)
        s += __shfl_xor_sync(0xffffffffu, s, off);
    if (lane == 0) wred[warp] = s;
    __syncthreads();
    if (warp == 0) {
        float t = wred[lane];
        #pragma unroll
        for (int off = 16; off > 0; off >>= 1)
            t += __shfl_xor_sync(0xffffffffu, t, off);
        if (lane == 0) out[0] = t * (1.0f / (float)BATCH);
    }
}

extern "C" void kernel_launch(void* const* d_in, const int* in_sizes, int n_in,
                              void* d_out, int out_size) {
    const void*  rt = d_in[0];                 // rt_batch [8192,128] int32 or int64
    const float* X  = (const float*)d_in[1];   // X float32 [100000,128]
    const int*   m  = (const int*)d_in[2];     // m scalar
    float* out = (float*)d_out;

    node2vec_row_kernel<<<BATCH, 128>>>(rt, X, m);
    node2vec_reduce_kernel<<<1, 1024>>>(out);
}

// round 5
// speedup vs baseline: 2.3315x; 1.1739x over previous
#include <cuda_runtime.h>

#define BATCH   8192
#define ROW_LEN 128
#define DIM     128

__device__ float g_partials[BATCH];

__global__ __launch_bounds__(128, 10)
void node2vec_row_kernel(const void* __restrict__ rt_raw,
                         const float* __restrict__ X,
                         const int* __restrict__ m_ptr) {
    const int b    = blockIdx.x;
    const int tid  = threadIdx.x;   // 0..127
    const int lane = tid & 31;
    const int warp = tid >> 5;      // 0..3

    __shared__ int   idx_s[ROW_LEN];
    __shared__ float x0s[DIM];
    __shared__ float scores[ROW_LEN];

    const int* __restrict__ rt32 = (const int*)rt_raw;

    // Runtime dtype detection: int64 (<2^31 values) => odd 32-bit words zero.
    const bool is64 = (rt32[1] == 0) & (rt32[3] == 0) & (rt32[5] == 0) & (rt32[7] == 0);

    const long long base = (long long)b * ROW_LEN;

    // Preload this row's 128 indices into shared (one coalesced pass).
    idx_s[tid] = is64 ? rt32[2 * (base + tid)] : rt32[base + tid];

    // x0 = X[rt[b,0]]
    {
        const long long e0 = is64 ? (long long)rt32[2 * base] : (long long)rt32[base];
        x0s[tid] = __ldg(X + e0 * DIM + tid);
    }
    __syncthreads();

    // Each lane holds x0 elements {lane, 32+lane, 64+lane, 96+lane}.
    const float x0c0 = x0s[lane];
    const float x0c1 = x0s[lane + 32];
    const float x0c2 = x0s[lane + 64];
    const float x0c3 = x0s[lane + 96];

    // Warp w handles rows w*32 .. w*32+31, 4 rows per iteration.
    // Every LDG touches exactly ONE 128B line (32 lanes x 4B contiguous)
    // -> 1.0 cyc/wavefront cross-LDG rate in L1tex (no within-LDG replays).
    const int row0 = warp * 32;
    #pragma unroll
    for (int it = 0; it < 8; ++it) {
        const int l = row0 + it * 4;
        const long long i0 = idx_s[l + 0];
        const long long i1 = idx_s[l + 1];
        const long long i2 = idx_s[l + 2];
        const long long i3 = idx_s[l + 3];
        const float* __restrict__ r0 = X + i0 * DIM + lane;
        const float* __restrict__ r1 = X + i1 * DIM + lane;
        const float* __restrict__ r2 = X + i2 * DIM + lane;
        const float* __restrict__ r3 = X + i3 * DIM + lane;

        // 16 independent 1-line loads (MLP=16), then FMAs.
        const float a0 = __ldg(r0), a1 = __ldg(r0 + 32), a2 = __ldg(r0 + 64), a3 = __ldg(r0 + 96);
        const float b0 = __ldg(r1), b1 = __ldg(r1 + 32), b2 = __ldg(r1 + 64), b3 = __ldg(r1 + 96);
        const float c0 = __ldg(r2), c1 = __ldg(r2 + 32), c2 = __ldg(r2 + 64), c3 = __ldg(r2 + 96);
        const float e0 = __ldg(r3), e1 = __ldg(r3 + 32), e2 = __ldg(r3 + 64), e3 = __ldg(r3 + 96);

        float d0 = a0 * x0c0 + a1 * x0c1 + a2 * x0c2 + a3 * x0c3;
        float d1 = b0 * x0c0 + b1 * x0c1 + b2 * x0c2 + b3 * x0c3;
        float d2 = c0 * x0c0 + c1 * x0c1 + c2 * x0c2 + c3 * x0c3;
        float d3 = e0 * x0c0 + e1 * x0c1 + e2 * x0c2 + e3 * x0c3;

        // Multi-row butterfly: 5 shfls reduce all 4 accumulators.
        // Level 1 (xor 16): low half keeps d0/d2 sums, high half d1/d3.
        float loA = (lane & 16) ? d1 : d0;
        float hiA = (lane & 16) ? d0 : d1;
        loA += __shfl_xor_sync(0xffffffffu, hiA, 16);
        float loB = (lane & 16) ? d3 : d2;
        float hiB = (lane & 16) ? d2 : d3;
        loB += __shfl_xor_sync(0xffffffffu, hiB, 16);
        // Level 2 (xor 8): merge A/B.
        float lo = (lane & 8) ? loB : loA;
        float hi = (lane & 8) ? loA : loB;
        lo += __shfl_xor_sync(0xffffffffu, hi, 8);
        // Levels 3-5: butterfly within 8-lane groups.
        #pragma unroll
        for (int off = 4; off > 0; off >>= 1)
            lo += __shfl_xor_sync(0xffffffffu, lo, off);

        // lane 0 -> row l+0, lane 8 -> l+2, lane 16 -> l+1, lane 24 -> l+3.
        if ((lane & 7) == 0) {
            const int g = lane >> 3;               // 0..3
            const int sel = (g & 1) * 2 + (g >> 1); // {0,2,1,3}
            scores[l + sel] = lo;
        }
    }
    __syncthreads();

    // Warp 0: softmax stats over 128 scores via shuffles.
    if (warp == 0) {
        const int m = m_ptr[0];     // low 32 bits of int32/int64 LE
        const float s0 = scores[lane];
        const float s1 = scores[lane + 32];
        const float s2 = scores[lane + 64];
        const float s3 = scores[lane + 96];

        float mx = fmaxf(fmaxf(s0, s1), fmaxf(s2, s3));
        #pragma unroll
        for (int off = 16; off > 0; off >>= 1)
            mx = fmaxf(mx, __shfl_xor_sync(0xffffffffu, mx, off));

        float e = __expf(s0 - mx) + __expf(s1 - mx) + __expf(s2 - mx) + __expf(s3 - mx);
        float p = 0.0f;
        if (lane >= 1 && lane <= m)        p += s0;
        if (lane + 32 <= m)                p += s1;
        if (lane + 64 <= m)                p += s2;
        if (lane + 96 <= m)                p += s3;
        #pragma unroll
        for (int off = 16; off > 0; off >>= 1) {
            e += __shfl_xor_sync(0xffffffffu, e, off);
            p += __shfl_xor_sync(0xffffffffu, p, off);
        }

        if (lane == 0) {
            const float lse = mx + __logf(e);
            g_partials[b] = (float)m * lse - p;
        }
    }
}

__global__ __launch_bounds__(1024)
void node2vec_reduce_kernel(float* __restrict__ out) {
    __shared__ float wred[32];
    const int tid  = threadIdx.x;
    const int lane = tid & 31;
    const int warp = tid >> 5;
    const float4* __restrict__ p4 = reinterpret_cast<const float4*>(g_partials);
    const float4 a = p4[tid];
    const float4 c = p4[tid + 1024];
    float s = (a.x + a.y) + (a.z + a.w) + (c.x + c.y) + (c.z + c.w);
    #pragma unroll
    for (int off = 16; off > 0; off >>= 1)
        s += __shfl_xor_sync(0xffffffffu, s, off);
    if (lane == 0) wred[warp] = s;
    __syncthreads();
    if (warp == 0) {
        float t = wred[lane];
        #pragma unroll
        for (int off = 16; off > 0; off >>= 1)
            t += __shfl_xor_sync(0xffffffffu, t, off);
        if (lane == 0) out[0] = t * (1.0f / (float)BATCH);
    }
}

extern "C" void kernel_launch(void* const* d_in, const int* in_sizes, int n_in,
                              void* d_out, int out_size) {
    const void*  rt = d_in[0];                 // rt_batch [8192,128] int32 or int64
    const float* X  = (const float*)d_in[1];   // X float32 [100000,128]
    const int*   m  = (const int*)d_in[2];     // m scalar
    float* out = (float*)d_out;

    node2vec_row_kernel<<<BATCH, 128>>>(rt, X, m);
    node2vec_reduce_kernel<<<1, 1024>>>(out);
}